// round 1
// baseline (speedup 1.0000x reference)
#include <cuda_runtime.h>
#include <math.h>
#include <stdint.h>

#define HEADS 4
#define DD 256
#define HD 1024            // HEADS * DD

#define MAXND 20000
#define MAXNI 4096
#define MAXED 640000
#define MAXET (MAXED + MAXND)

// ---------------- scratch (device globals; no allocation allowed) ----------
__device__ float g_hd  [(size_t)MAXND * HD];     // dialogue GAT hidden
__device__ float g_hi  [(size_t)MAXNI * HD];
__device__ float g_he  [(size_t)MAXNI * HD];
__device__ float g_ie  [(size_t)MAXNI * DD];     // gathered intention embeddings
__device__ float g_ee  [(size_t)MAXNI * DD];
__device__ float g_ssrc[(size_t)MAXND * HEADS];
__device__ float g_sdst[(size_t)MAXND * HEADS];
__device__ int   g_deg [MAXND];
__device__ int   g_off [MAXND + 1];
__device__ int   g_cur [MAXND];
__device__ int   g_csr [MAXET];
__device__ float g_gat [(size_t)MAXND * DD];     // GAT layer output (pre-FC)
__device__ float g_dd  [(size_t)MAXND * DD];     // d after relu-FC
__device__ float g_ii  [(size_t)MAXNI * DD];     // i after relu-FC
__device__ float g_ev  [(size_t)MAXNI * DD];     // e after relu-FC
__device__ float g_S   [(size_t)MAXND * 4096];   // attention scores scratch
__device__ float g_atti[(size_t)MAXND * DD];
__device__ float g_atte[(size_t)MAXND * DD];

// ---------------- generic fp32 GEMM: C = A @ B (+bias)(+relu) --------------
// A: [M,K] row-major. B: [K,N] row-major, or [N,K] row-major if TRANSB (C=A@B^T)
// 128x128 tile, BK=8, 256 threads, 8x8 per thread. Requires K%8==0 (and K%4
// for TRANSB). Row/col bounds guarded.
template<bool TRANSB, bool BIAS, bool RELU>
__global__ void gemm128(const float* __restrict__ A, const float* __restrict__ B,
                        float* __restrict__ C, const float* __restrict__ bias,
                        int M, int N, int K)
{
    __shared__ float As[8][128];
    __shared__ float Bs[8][128];
    const int tid = threadIdx.x;
    const int tx = tid & 15, ty = tid >> 4;
    const int row0 = blockIdx.y * 128, col0 = blockIdx.x * 128;

    float acc[8][8];
#pragma unroll
    for (int i = 0; i < 8; i++)
#pragma unroll
        for (int j = 0; j < 8; j++) acc[i][j] = 0.f;

    const int a_r = tid >> 1;
    const int a_c = (tid & 1) * 4;
    const int b_r = tid >> 5;          // NN: k row 0..7
    const int b_c = (tid & 31) * 4;    // NN: col
    const int t_c = tid >> 1;          // TRANSB: col 0..127
    const int t_k = (tid & 1) * 4;     // TRANSB: k

    for (int k0 = 0; k0 < K; k0 += 8) {
        float4 av = make_float4(0.f, 0.f, 0.f, 0.f);
        int ar = row0 + a_r;
        if (ar < M) av = *(const float4*)(A + (size_t)ar * K + k0 + a_c);
        As[a_c + 0][a_r] = av.x; As[a_c + 1][a_r] = av.y;
        As[a_c + 2][a_r] = av.z; As[a_c + 3][a_r] = av.w;

        if (!TRANSB) {
            float4 bv = make_float4(0.f, 0.f, 0.f, 0.f);
            int bc = col0 + b_c;
            if (bc < N) bv = *(const float4*)(B + (size_t)(k0 + b_r) * N + bc);
            Bs[b_r][b_c + 0] = bv.x; Bs[b_r][b_c + 1] = bv.y;
            Bs[b_r][b_c + 2] = bv.z; Bs[b_r][b_c + 3] = bv.w;
        } else {
            float4 bv = make_float4(0.f, 0.f, 0.f, 0.f);
            int bc = col0 + t_c;
            if (bc < N) bv = *(const float4*)(B + (size_t)bc * K + k0 + t_k);
            Bs[t_k + 0][t_c] = bv.x; Bs[t_k + 1][t_c] = bv.y;
            Bs[t_k + 2][t_c] = bv.z; Bs[t_k + 3][t_c] = bv.w;
        }
        __syncthreads();

#pragma unroll
        for (int kk = 0; kk < 8; kk++) {
            float a[8], b[8];
#pragma unroll
            for (int i = 0; i < 8; i++) a[i] = As[kk][ty * 8 + i];
#pragma unroll
            for (int j = 0; j < 8; j++) b[j] = Bs[kk][tx * 8 + j];
#pragma unroll
            for (int i = 0; i < 8; i++)
#pragma unroll
                for (int j = 0; j < 8; j++) acc[i][j] += a[i] * b[j];
        }
        __syncthreads();
    }

#pragma unroll
    for (int i = 0; i < 8; i++) {
        int r = row0 + ty * 8 + i;
        if (r >= M) continue;
#pragma unroll
        for (int j = 0; j < 8; j++) {
            int c = col0 + tx * 8 + j;
            if (c >= N) continue;
            float v = acc[i][j];
            if (BIAS) v += bias[c];
            if (RELU) v = fmaxf(v, 0.f);
            C[(size_t)r * N + c] = v;
        }
    }
}

// ---------------- misc small kernels ---------------------------------------
__global__ void k_gather_emb(const float* __restrict__ table, const int* __restrict__ idx,
                             float* __restrict__ out, int N)
{
    int i = blockIdx.x * blockDim.x + threadIdx.x;
    int total = N * DD;
    for (; i < total; i += gridDim.x * blockDim.x) {
        int n = i / DD, c = i - n * DD;
        out[i] = table[(size_t)idx[n] * DD + c];
    }
}

// per-node attention scores: s_src[n][h] = sum_c h[n,h,c]*a_src[h,c]; same for dst
__global__ void k_scores(const float* __restrict__ h, const float* __restrict__ a_src,
                         const float* __restrict__ a_dst,
                         float* __restrict__ ssrc, float* __restrict__ sdst, int N)
{
    int n = blockIdx.x;
    int tid = threadIdx.x;        // 128
    int hh = tid >> 5, lane = tid & 31;
    const float* hr = h + (size_t)n * HD + hh * DD;
    float s1 = 0.f, s2 = 0.f;
    for (int c = lane; c < DD; c += 32) {
        float v = hr[c];
        s1 += v * a_src[hh * DD + c];
        s2 += v * a_dst[hh * DD + c];
    }
#pragma unroll
    for (int o = 16; o > 0; o >>= 1) {
        s1 += __shfl_down_sync(0xffffffffu, s1, o);
        s2 += __shfl_down_sync(0xffffffffu, s2, o);
    }
    if (lane == 0) { ssrc[n * HEADS + hh] = s1; sdst[n * HEADS + hh] = s2; }
}

__global__ void k_set_deg1(int* deg, int N)
{
    int i = blockIdx.x * blockDim.x + threadIdx.x;
    if (i < N) deg[i] = 1;     // self loop
}
__global__ void k_count(const int* __restrict__ dst, int* __restrict__ deg, int E)
{
    int i = blockIdx.x * blockDim.x + threadIdx.x;
    for (; i < E; i += gridDim.x * blockDim.x) atomicAdd(&deg[dst[i]], 1);
}
__global__ void k_exscan(const int* __restrict__ deg, int* __restrict__ off,
                         int* __restrict__ cur, int N)
{
    __shared__ int sh[1024];
    __shared__ int carry;
    int tid = threadIdx.x;
    if (tid == 0) carry = 0;
    __syncthreads();
    for (int base = 0; base < N; base += 1024) {
        int i = base + tid;
        int v = (i < N) ? deg[i] : 0;
        sh[tid] = v;
        __syncthreads();
        for (int ofs = 1; ofs < 1024; ofs <<= 1) {
            int t = (tid >= ofs) ? sh[tid - ofs] : 0;
            __syncthreads();
            sh[tid] += t;
            __syncthreads();
        }
        int excl = carry + sh[tid] - v;
        if (i < N) { off[i] = excl; cur[i] = excl; }
        __syncthreads();
        if (tid == 0) carry += sh[1023];
        __syncthreads();
    }
    if (tid == 0) off[N] = carry;
}
__global__ void k_fill(const int* __restrict__ src, const int* __restrict__ dst,
                       int* __restrict__ cur, int* __restrict__ csr, int E)
{
    int i = blockIdx.x * blockDim.x + threadIdx.x;
    for (; i < E; i += gridDim.x * blockDim.x) {
        int p = atomicAdd(&cur[dst[i]], 1);
        csr[p] = src[i];
    }
}
__global__ void k_fill_self(int* __restrict__ cur, int* __restrict__ csr, int N)
{
    int i = blockIdx.x * blockDim.x + threadIdx.x;
    if (i < N) { int p = atomicAdd(&cur[i], 1); csr[p] = i; }
}

// ---------------- GAT aggregation: one block per destination node ----------
#define AGG_CHUNK 512
__global__ void k_gat_agg(const float* __restrict__ h,      // [N, HD]
                          const float* __restrict__ ssrc,   // [N, 4]
                          const float* __restrict__ sdst,   // [N, 4]
                          const int* __restrict__ off, const int* __restrict__ csr,
                          const float* __restrict__ bias,   // [256]
                          float* __restrict__ out, int N)   // [N, 256]
{
    const int n = blockIdx.x;
    const int tid = threadIdx.x;      // 256
    const int e0 = off[n], e1 = off[n + 1];

    __shared__ int    s_src[AGG_CHUNK];
    __shared__ float  s_w[AGG_CHUNK * 4];
    __shared__ float4 red[256];
    __shared__ float  s_m[4], s_s[4];
    __shared__ float  s_out[1024];

    float sd[4];
#pragma unroll
    for (int hh = 0; hh < 4; hh++) sd[hh] = sdst[n * 4 + hh];

    // pass 1: per-head max of leaky_relu(ssrc[src]+sdst[n])
    float mloc[4] = {-1e30f, -1e30f, -1e30f, -1e30f};
    for (int e = e0 + tid; e < e1; e += 256) {
        int s = csr[e];
#pragma unroll
        for (int hh = 0; hh < 4; hh++) {
            float v = ssrc[s * 4 + hh] + sd[hh];
            v = v > 0.f ? v : 0.2f * v;
            mloc[hh] = fmaxf(mloc[hh], v);
        }
    }
    red[tid] = make_float4(mloc[0], mloc[1], mloc[2], mloc[3]);
    __syncthreads();
    for (int s = 128; s > 0; s >>= 1) {
        if (tid < s) {
            float4 a = red[tid], b = red[tid + s];
            a.x = fmaxf(a.x, b.x); a.y = fmaxf(a.y, b.y);
            a.z = fmaxf(a.z, b.z); a.w = fmaxf(a.w, b.w);
            red[tid] = a;
        }
        __syncthreads();
    }
    if (tid < 4) s_m[tid] = ((float*)&red[0])[tid];
    __syncthreads();
    float m0 = s_m[0], m1 = s_m[1], m2 = s_m[2], m3 = s_m[3];

    // pass 2: w = exp(e - m); accumulate sum(w) and weighted feature sum
    const int hh_ = tid >> 6;          // head owned by this thread
    const int cb  = tid & 63;          // base channel within head
    float acc0 = 0.f, acc1 = 0.f, acc2 = 0.f, acc3 = 0.f;
    float wsum[4] = {0.f, 0.f, 0.f, 0.f};

    for (int c0 = e0; c0 < e1; c0 += AGG_CHUNK) {
        int cnt = min(AGG_CHUNK, e1 - c0);
        for (int j = tid; j < cnt; j += 256) {
            int s = csr[c0 + j];
            s_src[j] = s;
            float v0 = ssrc[s * 4 + 0] + sd[0]; v0 = v0 > 0.f ? v0 : 0.2f * v0;
            float v1 = ssrc[s * 4 + 1] + sd[1]; v1 = v1 > 0.f ? v1 : 0.2f * v1;
            float v2 = ssrc[s * 4 + 2] + sd[2]; v2 = v2 > 0.f ? v2 : 0.2f * v2;
            float v3 = ssrc[s * 4 + 3] + sd[3]; v3 = v3 > 0.f ? v3 : 0.2f * v3;
            float w0 = __expf(v0 - m0), w1 = __expf(v1 - m1);
            float w2 = __expf(v2 - m2), w3 = __expf(v3 - m3);
            s_w[j * 4 + 0] = w0; s_w[j * 4 + 1] = w1;
            s_w[j * 4 + 2] = w2; s_w[j * 4 + 3] = w3;
            wsum[0] += w0; wsum[1] += w1; wsum[2] += w2; wsum[3] += w3;
        }
        __syncthreads();
        for (int j = 0; j < cnt; j++) {
            int s = s_src[j];
            float w = s_w[j * 4 + hh_];
            const float* hr = h + (size_t)s * HD + hh_ * DD + cb;
            acc0 += w * hr[0];
            acc1 += w * hr[64];
            acc2 += w * hr[128];
            acc3 += w * hr[192];
        }
        __syncthreads();
    }

    // reduce w sums
    red[tid] = make_float4(wsum[0], wsum[1], wsum[2], wsum[3]);
    __syncthreads();
    for (int s = 128; s > 0; s >>= 1) {
        if (tid < s) {
            float4 a = red[tid], b = red[tid + s];
            a.x += b.x; a.y += b.y; a.z += b.z; a.w += b.w;
            red[tid] = a;
        }
        __syncthreads();
    }
    if (tid < 4) s_s[tid] = ((float*)&red[0])[tid];

    s_out[hh_ * 256 + cb]       = acc0;
    s_out[hh_ * 256 + cb + 64]  = acc1;
    s_out[hh_ * 256 + cb + 128] = acc2;
    s_out[hh_ * 256 + cb + 192] = acc3;
    __syncthreads();

    {
        int c = tid;
        float r = 0.f;
#pragma unroll
        for (int hh = 0; hh < 4; hh++)
            r += s_out[hh * 256 + c] / (s_s[hh] + 1e-16f);
        out[(size_t)n * DD + c] = 0.25f * r + bias[c];
    }
}

// ---------------- row softmax (N=4096) -------------------------------------
__global__ void k_softmax(float* __restrict__ S, int cols)
{
    int r = blockIdx.x;
    float* row = S + (size_t)r * cols;
    int tid = threadIdx.x;   // 256
    __shared__ float red[256];

    float m = -1e30f;
    for (int c = tid; c < cols; c += 256) m = fmaxf(m, row[c]);
    red[tid] = m; __syncthreads();
    for (int s = 128; s > 0; s >>= 1) {
        if (tid < s) red[tid] = fmaxf(red[tid], red[tid + s]);
        __syncthreads();
    }
    m = red[0]; __syncthreads();

    float sum = 0.f;
    for (int c = tid; c < cols; c += 256) {
        float v = __expf(row[c] - m);
        row[c] = v;
        sum += v;
    }
    red[tid] = sum; __syncthreads();
    for (int s = 128; s > 0; s >>= 1) {
        if (tid < s) red[tid] += red[tid + s];
        __syncthreads();
    }
    float inv = 1.f / red[0];
    for (int c = tid; c < cols; c += 256) row[c] *= inv;
}

// ---------------- fused concat + final FC ([768] -> 32) --------------------
__global__ void k_final(const float* __restrict__ d, const float* __restrict__ ai,
                        const float* __restrict__ ae, const float* __restrict__ W,
                        const float* __restrict__ b, float* __restrict__ out, int M)
{
    __shared__ float s_in[8][768];
    int r0 = blockIdx.x * 8;
    int tid = threadIdx.x;   // 256
    for (int idx = tid; idx < 8 * 768; idx += 256) {
        int rr = idx / 768, cc = idx - rr * 768;
        int r = r0 + rr;
        float v = 0.f;
        if (r < M) {
            if (cc < 256)      v = d [(size_t)r * 256 + cc];
            else if (cc < 512) v = ai[(size_t)r * 256 + cc - 256];
            else               v = ae[(size_t)r * 256 + cc - 512];
        }
        s_in[rr][cc] = v;
    }
    __syncthreads();
    int rr = tid >> 5, j = tid & 31;
    int r = r0 + rr;
    if (r < M) {
        float acc = b[j];
#pragma unroll 8
        for (int k = 0; k < 768; k++) acc += s_in[rr][k] * W[k * 32 + j];
        out[(size_t)r * 32 + j] = acc;
    }
}

// ---------------- host orchestration ---------------------------------------
static inline void launch_gemm(const float* A, const float* B, float* C,
                               const float* bias, int M, int N, int K,
                               bool transb, bool do_bias, bool relu)
{
    dim3 grid((N + 127) / 128, (M + 127) / 128);
    if (!transb) {
        if (do_bias && relu) gemm128<false, true,  true ><<<grid, 256>>>(A, B, C, bias, M, N, K);
        else                 gemm128<false, false, false><<<grid, 256>>>(A, B, C, bias, M, N, K);
    } else {
        gemm128<true, false, false><<<grid, 256>>>(A, B, C, bias, M, N, K);
    }
}

struct Ptrs {
    float *hd, *hi, *he, *ie, *ee, *ssrc, *sdst, *gat, *dd, *ii, *ev, *S, *atti, *atte;
    int *deg, *off, *cur, *csr;
};

static void run_gat(const float* x, const float* W, const float* a_src,
                    const float* a_dst, const float* bias,
                    const int* esrc, const int* edst,
                    int N, int E, int Din, float* hbuf, float* gat_out, const Ptrs& p)
{
    launch_gemm(x, W, hbuf, nullptr, N, HD, Din, false, false, false);
    k_scores<<<N, 128>>>(hbuf, a_src, a_dst, p.ssrc, p.sdst, N);
    k_set_deg1<<<(N + 255) / 256, 256>>>(p.deg, N);
    k_count<<<(E + 255) / 256 > 2048 ? 2048 : (E + 255) / 256, 256>>>(edst, p.deg, E);
    k_exscan<<<1, 1024>>>(p.deg, p.off, p.cur, N);
    k_fill<<<(E + 255) / 256 > 2048 ? 2048 : (E + 255) / 256, 256>>>(esrc, edst, p.cur, p.csr, E);
    k_fill_self<<<(N + 255) / 256, 256>>>(p.cur, p.csr, N);
    k_gat_agg<<<N, 256>>>(hbuf, p.ssrc, p.sdst, p.off, p.csr, bias, gat_out, N);
}

extern "C" void kernel_launch(void* const* d_in, const int* in_sizes, int n_in,
                              void* d_out, int out_size)
{
    const float* x_d     = (const float*)d_in[0];
    const int*   idx_i   = (const int*)  d_in[1];
    const int*   idx_e   = (const int*)  d_in[2];
    const int*   eidx_d  = (const int*)  d_in[3];
    const int*   eidx_i  = (const int*)  d_in[4];
    const int*   eidx_e  = (const int*)  d_in[5];
    const float* emb_i   = (const float*)d_in[6];
    const float* emb_e   = (const float*)d_in[7];
    const float* Wd      = (const float*)d_in[8];
    const float* a_src_d = (const float*)d_in[9];
    const float* a_dst_d = (const float*)d_in[10];
    const float* bd      = (const float*)d_in[11];
    const float* Wi      = (const float*)d_in[12];
    const float* a_src_i = (const float*)d_in[13];
    const float* a_dst_i = (const float*)d_in[14];
    const float* bi      = (const float*)d_in[15];
    const float* We      = (const float*)d_in[16];
    const float* a_src_e = (const float*)d_in[17];
    const float* a_dst_e = (const float*)d_in[18];
    const float* be      = (const float*)d_in[19];
    const float* W_dfc   = (const float*)d_in[20];
    const float* b_dfc   = (const float*)d_in[21];
    const float* W_ifc   = (const float*)d_in[22];
    const float* b_ifc   = (const float*)d_in[23];
    const float* W_efc   = (const float*)d_in[24];
    const float* b_efc   = (const float*)d_in[25];
    const float* W_fc    = (const float*)d_in[26];
    const float* b_fc    = (const float*)d_in[27];
    float* out = (float*)d_out;

    const int Din = 512;
    const int Nd = in_sizes[0] / Din;
    const int Ni = in_sizes[1];
    const int Ne = in_sizes[2];
    const int Ed = in_sizes[3] / 2;
    const int Ei = in_sizes[4] / 2;
    const int Ee = in_sizes[5] / 2;

    Ptrs p;
    cudaGetSymbolAddress((void**)&p.hd,   g_hd);
    cudaGetSymbolAddress((void**)&p.hi,   g_hi);
    cudaGetSymbolAddress((void**)&p.he,   g_he);
    cudaGetSymbolAddress((void**)&p.ie,   g_ie);
    cudaGetSymbolAddress((void**)&p.ee,   g_ee);
    cudaGetSymbolAddress((void**)&p.ssrc, g_ssrc);
    cudaGetSymbolAddress((void**)&p.sdst, g_sdst);
    cudaGetSymbolAddress((void**)&p.gat,  g_gat);
    cudaGetSymbolAddress((void**)&p.dd,   g_dd);
    cudaGetSymbolAddress((void**)&p.ii,   g_ii);
    cudaGetSymbolAddress((void**)&p.ev,   g_ev);
    cudaGetSymbolAddress((void**)&p.S,    g_S);
    cudaGetSymbolAddress((void**)&p.atti, g_atti);
    cudaGetSymbolAddress((void**)&p.atte, g_atte);
    cudaGetSymbolAddress((void**)&p.deg,  g_deg);
    cudaGetSymbolAddress((void**)&p.off,  g_off);
    cudaGetSymbolAddress((void**)&p.cur,  g_cur);
    cudaGetSymbolAddress((void**)&p.csr,  g_csr);

    // embedding lookups
    k_gather_emb<<<2048, 256>>>(emb_i, idx_i, p.ie, Ni);
    k_gather_emb<<<2048, 256>>>(emb_e, idx_e, p.ee, Ne);

    // dialogue branch: GAT + relu FC
    run_gat(x_d, Wd, a_src_d, a_dst_d, bd, eidx_d, eidx_d + Ed, Nd, Ed, Din, p.hd, p.gat, p);
    launch_gemm(p.gat, W_dfc, p.dd, b_dfc, Nd, DD, DD, false, true, true);

    // intention branch
    run_gat(p.ie, Wi, a_src_i, a_dst_i, bi, eidx_i, eidx_i + Ei, Ni, Ei, DD, p.hi, p.gat, p);
    launch_gemm(p.gat, W_ifc, p.ii, b_ifc, Ni, DD, DD, false, true, true);

    // emotion branch
    run_gat(p.ee, We, a_src_e, a_dst_e, be, eidx_e, eidx_e + Ee, Ne, Ee, DD, p.he, p.gat, p);
    launch_gemm(p.gat, W_efc, p.ev, b_efc, Ne, DD, DD, false, true, true);

    // cross attention: att_i = softmax(d @ i^T) @ i
    launch_gemm(p.dd, p.ii, p.S, nullptr, Nd, Ni, DD, true, false, false);
    k_softmax<<<Nd, 256>>>(p.S, Ni);
    launch_gemm(p.S, p.ii, p.atti, nullptr, Nd, DD, Ni, false, false, false);

    // att_e = softmax(d @ e^T) @ e
    launch_gemm(p.dd, p.ev, p.S, nullptr, Nd, Ne, DD, true, false, false);
    k_softmax<<<Nd, 256>>>(p.S, Ne);
    launch_gemm(p.S, p.ev, p.atte, nullptr, Nd, DD, Ne, false, false, false);

    // fused concat + final FC
    k_final<<<(Nd + 7) / 8, 256>>>(p.dd, p.atti, p.atte, W_fc, b_fc, out, Nd);
}

// round 2
// speedup vs baseline: 2.3776x; 2.3776x over previous
#include <cuda_runtime.h>
#include <math.h>
#include <stdint.h>

#define HEADS 4
#define DD 256
#define HD 1024            // HEADS * DD

#define MAXND 20000
#define MAXNI 4096
#define MAXED 640000
#define MAXET (MAXED + MAXND)

// ---------------- scratch (device globals; no allocation allowed) ----------
__device__ float g_hd  [(size_t)MAXND * HD];     // dialogue GAT hidden
__device__ float g_hi  [(size_t)MAXNI * HD];
__device__ float g_he  [(size_t)MAXNI * HD];
__device__ float g_ie  [(size_t)MAXNI * DD];     // gathered intention embeddings
__device__ float g_ee  [(size_t)MAXNI * DD];
__device__ float g_ssrc[(size_t)MAXND * HEADS];
__device__ float g_sdst[(size_t)MAXND * HEADS];
__device__ int   g_deg [MAXND];
__device__ int   g_off [MAXND + 1];
__device__ int   g_cur [MAXND];
__device__ int   g_csr [MAXET];
__device__ float g_gat [(size_t)MAXND * DD];     // GAT layer output (pre-FC)
__device__ float g_dd  [(size_t)MAXND * DD];     // d after relu-FC
__device__ float g_ii  [(size_t)MAXNI * DD];     // i after relu-FC
__device__ float g_ev  [(size_t)MAXNI * DD];     // e after relu-FC
__device__ float g_S   [(size_t)MAXND * 4096];   // attention scores scratch
__device__ float g_atti[(size_t)MAXND * DD];
__device__ float g_atte[(size_t)MAXND * DD];

// ---------------- tf32 tensor-core GEMM ------------------------------------
// C[M,N] = A[M,K] @ B   (B: [K,N] row-major, or [N,K] row-major if TRANSB)
// BM=BN=128, BK=16, 256 threads = 8 warps (4x2), warp tile 32x64 via
// m16n8k8.tf32 mma.sync. K % 16 == 0, N % 128 == 0 required. M guarded.

__device__ __forceinline__ uint32_t f2tf(float f) {
    uint32_t u;
    asm("cvt.rna.tf32.f32 %0, %1;" : "=r"(u) : "f"(f));
    return u;
}

template<bool TRANSB, bool BIAS, bool RELU>
__global__ __launch_bounds__(256)
void tgemm(const float* __restrict__ A, const float* __restrict__ B,
           float* __restrict__ C, const float* __restrict__ bias,
           int M, int N, int K)
{
    __shared__ uint32_t As[16][132];   // [k][m]
    __shared__ uint32_t Bs[16][132];   // [k][n]

    const int tid  = threadIdx.x;
    const int warp = tid >> 5, lane = tid & 31;
    const int g    = lane >> 2, tig = lane & 3;
    const int wm   = (warp >> 1) * 32;     // warp row offset in tile
    const int wn   = (warp & 1) * 64;      // warp col offset in tile
    const int row0 = blockIdx.y * 128, col0 = blockIdx.x * 128;

    float c[2][8][4];
#pragma unroll
    for (int i = 0; i < 2; i++)
#pragma unroll
        for (int j = 0; j < 8; j++)
#pragma unroll
            for (int q = 0; q < 4; q++) c[i][j][q] = 0.f;

    float4 a4[2], b4[2];
    const float4 z4 = make_float4(0.f, 0.f, 0.f, 0.f);

    // ---- prefetch k0 = 0 ----
    {
        const int k0 = 0;
#pragma unroll
        for (int i = 0; i < 2; i++) {
            int f  = tid + 256 * i;
            int ar = f >> 2, ac = (f & 3) * 4;
            int r  = row0 + ar;
            a4[i] = (r < M) ? *(const float4*)(A + (size_t)r * K + k0 + ac) : z4;
            if (TRANSB) {
                int br = f >> 2, bc = (f & 3) * 4;
                b4[i] = *(const float4*)(B + (size_t)(col0 + br) * K + k0 + bc);
            } else {
                int bk = f >> 5, bn = (f & 31) * 4;
                b4[i] = *(const float4*)(B + (size_t)(k0 + bk) * N + col0 + bn);
            }
        }
    }

    for (int k0 = 0; k0 < K; k0 += 16) {
        // ---- store staged regs to smem (tf32-converted) ----
#pragma unroll
        for (int i = 0; i < 2; i++) {
            int f  = tid + 256 * i;
            int ar = f >> 2, ac = (f & 3) * 4;
            As[ac + 0][ar] = f2tf(a4[i].x);
            As[ac + 1][ar] = f2tf(a4[i].y);
            As[ac + 2][ar] = f2tf(a4[i].z);
            As[ac + 3][ar] = f2tf(a4[i].w);
            if (TRANSB) {
                int br = f >> 2, bc = (f & 3) * 4;
                Bs[bc + 0][br] = f2tf(b4[i].x);
                Bs[bc + 1][br] = f2tf(b4[i].y);
                Bs[bc + 2][br] = f2tf(b4[i].z);
                Bs[bc + 3][br] = f2tf(b4[i].w);
            } else {
                int bk = f >> 5, bn = (f & 31) * 4;
                Bs[bk][bn + 0] = f2tf(b4[i].x);
                Bs[bk][bn + 1] = f2tf(b4[i].y);
                Bs[bk][bn + 2] = f2tf(b4[i].z);
                Bs[bk][bn + 3] = f2tf(b4[i].w);
            }
        }
        __syncthreads();

        // ---- prefetch next tile ----
        if (k0 + 16 < K) {
            const int kn = k0 + 16;
#pragma unroll
            for (int i = 0; i < 2; i++) {
                int f  = tid + 256 * i;
                int ar = f >> 2, ac = (f & 3) * 4;
                int r  = row0 + ar;
                a4[i] = (r < M) ? *(const float4*)(A + (size_t)r * K + kn + ac) : z4;
                if (TRANSB) {
                    int br = f >> 2, bc = (f & 3) * 4;
                    b4[i] = *(const float4*)(B + (size_t)(col0 + br) * K + kn + bc);
                } else {
                    int bk = f >> 5, bn = (f & 31) * 4;
                    b4[i] = *(const float4*)(B + (size_t)(kn + bk) * N + col0 + bn);
                }
            }
        }

        // ---- compute: 2 k-steps of 8 ----
#pragma unroll
        for (int ks = 0; ks < 2; ks++) {
            const int kk = ks * 8;
            uint32_t af[2][4], bf[8][2];
#pragma unroll
            for (int i = 0; i < 2; i++) {
                int m = wm + i * 16 + g;
                af[i][0] = As[kk + tig][m];
                af[i][1] = As[kk + tig][m + 8];
                af[i][2] = As[kk + tig + 4][m];
                af[i][3] = As[kk + tig + 4][m + 8];
            }
#pragma unroll
            for (int j = 0; j < 8; j++) {
                int n = wn + j * 8 + g;
                bf[j][0] = Bs[kk + tig][n];
                bf[j][1] = Bs[kk + tig + 4][n];
            }
#pragma unroll
            for (int i = 0; i < 2; i++)
#pragma unroll
                for (int j = 0; j < 8; j++) {
                    asm volatile(
                        "mma.sync.aligned.m16n8k8.row.col.f32.tf32.tf32.f32 "
                        "{%0,%1,%2,%3}, {%4,%5,%6,%7}, {%8,%9}, {%0,%1,%2,%3};"
                        : "+f"(c[i][j][0]), "+f"(c[i][j][1]),
                          "+f"(c[i][j][2]), "+f"(c[i][j][3])
                        : "r"(af[i][0]), "r"(af[i][1]), "r"(af[i][2]), "r"(af[i][3]),
                          "r"(bf[j][0]), "r"(bf[j][1]));
                }
        }
        __syncthreads();
    }

    // ---- epilogue ----
#pragma unroll
    for (int i = 0; i < 2; i++) {
        int r0 = row0 + wm + i * 16 + g;
        int r1 = r0 + 8;
#pragma unroll
        for (int j = 0; j < 8; j++) {
            int cc = col0 + wn + j * 8 + tig * 2;
            float v0 = c[i][j][0], v1 = c[i][j][1];
            float v2 = c[i][j][2], v3 = c[i][j][3];
            if (BIAS) {
                float bb0 = bias[cc], bb1 = bias[cc + 1];
                v0 += bb0; v1 += bb1; v2 += bb0; v3 += bb1;
            }
            if (RELU) {
                v0 = fmaxf(v0, 0.f); v1 = fmaxf(v1, 0.f);
                v2 = fmaxf(v2, 0.f); v3 = fmaxf(v3, 0.f);
            }
            if (r0 < M) *(float2*)(C + (size_t)r0 * N + cc) = make_float2(v0, v1);
            if (r1 < M) *(float2*)(C + (size_t)r1 * N + cc) = make_float2(v2, v3);
        }
    }
}

// ---------------- misc small kernels ---------------------------------------
__global__ void k_gather_emb(const float* __restrict__ table, const int* __restrict__ idx,
                             float* __restrict__ out, int N)
{
    int i = blockIdx.x * blockDim.x + threadIdx.x;
    int total = N * DD;
    for (; i < total; i += gridDim.x * blockDim.x) {
        int n = i / DD, c = i - n * DD;
        out[i] = table[(size_t)idx[n] * DD + c];
    }
}

__global__ void k_scores(const float* __restrict__ h, const float* __restrict__ a_src,
                         const float* __restrict__ a_dst,
                         float* __restrict__ ssrc, float* __restrict__ sdst, int N)
{
    int n = blockIdx.x;
    int tid = threadIdx.x;        // 128
    int hh = tid >> 5, lane = tid & 31;
    const float* hr = h + (size_t)n * HD + hh * DD;
    float s1 = 0.f, s2 = 0.f;
    for (int c = lane; c < DD; c += 32) {
        float v = hr[c];
        s1 += v * a_src[hh * DD + c];
        s2 += v * a_dst[hh * DD + c];
    }
#pragma unroll
    for (int o = 16; o > 0; o >>= 1) {
        s1 += __shfl_down_sync(0xffffffffu, s1, o);
        s2 += __shfl_down_sync(0xffffffffu, s2, o);
    }
    if (lane == 0) { ssrc[n * HEADS + hh] = s1; sdst[n * HEADS + hh] = s2; }
}

__global__ void k_set_deg1(int* deg, int N)
{
    int i = blockIdx.x * blockDim.x + threadIdx.x;
    if (i < N) deg[i] = 1;     // self loop
}
__global__ void k_count(const int* __restrict__ dst, int* __restrict__ deg, int E)
{
    int i = blockIdx.x * blockDim.x + threadIdx.x;
    for (; i < E; i += gridDim.x * blockDim.x) atomicAdd(&deg[dst[i]], 1);
}
__global__ void k_exscan(const int* __restrict__ deg, int* __restrict__ off,
                         int* __restrict__ cur, int N)
{
    __shared__ int sh[1024];
    __shared__ int carry;
    int tid = threadIdx.x;
    if (tid == 0) carry = 0;
    __syncthreads();
    for (int base = 0; base < N; base += 1024) {
        int i = base + tid;
        int v = (i < N) ? deg[i] : 0;
        sh[tid] = v;
        __syncthreads();
        for (int ofs = 1; ofs < 1024; ofs <<= 1) {
            int t = (tid >= ofs) ? sh[tid - ofs] : 0;
            __syncthreads();
            sh[tid] += t;
            __syncthreads();
        }
        int excl = carry + sh[tid] - v;
        if (i < N) { off[i] = excl; cur[i] = excl; }
        __syncthreads();
        if (tid == 0) carry += sh[1023];
        __syncthreads();
    }
    if (tid == 0) off[N] = carry;
}
__global__ void k_fill(const int* __restrict__ src, const int* __restrict__ dst,
                       int* __restrict__ cur, int* __restrict__ csr, int E)
{
    int i = blockIdx.x * blockDim.x + threadIdx.x;
    for (; i < E; i += gridDim.x * blockDim.x) {
        int p = atomicAdd(&cur[dst[i]], 1);
        csr[p] = src[i];
    }
}
__global__ void k_fill_self(int* __restrict__ cur, int* __restrict__ csr, int N)
{
    int i = blockIdx.x * blockDim.x + threadIdx.x;
    if (i < N) { int p = atomicAdd(&cur[i], 1); csr[p] = i; }
}

// ---------------- GAT aggregation: one block per destination node ----------
#define AGG_CHUNK 512
__global__ void k_gat_agg(const float* __restrict__ h,      // [N, HD]
                          const float* __restrict__ ssrc,   // [N, 4]
                          const float* __restrict__ sdst,   // [N, 4]
                          const int* __restrict__ off, const int* __restrict__ csr,
                          const float* __restrict__ bias,   // [256]
                          float* __restrict__ out, int N)   // [N, 256]
{
    const int n = blockIdx.x;
    const int tid = threadIdx.x;      // 256
    const int e0 = off[n], e1 = off[n + 1];

    __shared__ int    s_src[AGG_CHUNK];
    __shared__ float  s_w[AGG_CHUNK * 4];
    __shared__ float4 red[256];
    __shared__ float  s_m[4], s_s[4];
    __shared__ float  s_out[1024];

    float sd[4];
#pragma unroll
    for (int hh = 0; hh < 4; hh++) sd[hh] = sdst[n * 4 + hh];

    float mloc[4] = {-1e30f, -1e30f, -1e30f, -1e30f};
    for (int e = e0 + tid; e < e1; e += 256) {
        int s = csr[e];
#pragma unroll
        for (int hh = 0; hh < 4; hh++) {
            float v = ssrc[s * 4 + hh] + sd[hh];
            v = v > 0.f ? v : 0.2f * v;
            mloc[hh] = fmaxf(mloc[hh], v);
        }
    }
    red[tid] = make_float4(mloc[0], mloc[1], mloc[2], mloc[3]);
    __syncthreads();
    for (int s = 128; s > 0; s >>= 1) {
        if (tid < s) {
            float4 a = red[tid], b = red[tid + s];
            a.x = fmaxf(a.x, b.x); a.y = fmaxf(a.y, b.y);
            a.z = fmaxf(a.z, b.z); a.w = fmaxf(a.w, b.w);
            red[tid] = a;
        }
        __syncthreads();
    }
    if (tid < 4) s_m[tid] = ((float*)&red[0])[tid];
    __syncthreads();
    float m0 = s_m[0], m1 = s_m[1], m2 = s_m[2], m3 = s_m[3];

    const int hh_ = tid >> 6;
    const int cb  = tid & 63;
    float acc0 = 0.f, acc1 = 0.f, acc2 = 0.f, acc3 = 0.f;
    float wsum[4] = {0.f, 0.f, 0.f, 0.f};

    for (int c0 = e0; c0 < e1; c0 += AGG_CHUNK) {
        int cnt = min(AGG_CHUNK, e1 - c0);
        for (int j = tid; j < cnt; j += 256) {
            int s = csr[c0 + j];
            s_src[j] = s;
            float v0 = ssrc[s * 4 + 0] + sd[0]; v0 = v0 > 0.f ? v0 : 0.2f * v0;
            float v1 = ssrc[s * 4 + 1] + sd[1]; v1 = v1 > 0.f ? v1 : 0.2f * v1;
            float v2 = ssrc[s * 4 + 2] + sd[2]; v2 = v2 > 0.f ? v2 : 0.2f * v2;
            float v3 = ssrc[s * 4 + 3] + sd[3]; v3 = v3 > 0.f ? v3 : 0.2f * v3;
            float w0 = __expf(v0 - m0), w1 = __expf(v1 - m1);
            float w2 = __expf(v2 - m2), w3 = __expf(v3 - m3);
            s_w[j * 4 + 0] = w0; s_w[j * 4 + 1] = w1;
            s_w[j * 4 + 2] = w2; s_w[j * 4 + 3] = w3;
            wsum[0] += w0; wsum[1] += w1; wsum[2] += w2; wsum[3] += w3;
        }
        __syncthreads();
        for (int j = 0; j < cnt; j++) {
            int s = s_src[j];
            float w = s_w[j * 4 + hh_];
            const float* hr = h + (size_t)s * HD + hh_ * DD + cb;
            acc0 += w * hr[0];
            acc1 += w * hr[64];
            acc2 += w * hr[128];
            acc3 += w * hr[192];
        }
        __syncthreads();
    }

    red[tid] = make_float4(wsum[0], wsum[1], wsum[2], wsum[3]);
    __syncthreads();
    for (int s = 128; s > 0; s >>= 1) {
        if (tid < s) {
            float4 a = red[tid], b = red[tid + s];
            a.x += b.x; a.y += b.y; a.z += b.z; a.w += b.w;
            red[tid] = a;
        }
        __syncthreads();
    }
    if (tid < 4) s_s[tid] = ((float*)&red[0])[tid];

    s_out[hh_ * 256 + cb]       = acc0;
    s_out[hh_ * 256 + cb + 64]  = acc1;
    s_out[hh_ * 256 + cb + 128] = acc2;
    s_out[hh_ * 256 + cb + 192] = acc3;
    __syncthreads();

    {
        int c = tid;
        float r = 0.f;
#pragma unroll
        for (int hh = 0; hh < 4; hh++)
            r += s_out[hh * 256 + c] / (s_s[hh] + 1e-16f);
        out[(size_t)n * DD + c] = 0.25f * r + bias[c];
    }
}

// ---------------- row softmax (N=4096) -------------------------------------
__global__ void k_softmax(float* __restrict__ S, int cols)
{
    int r = blockIdx.x;
    float* row = S + (size_t)r * cols;
    int tid = threadIdx.x;   // 256
    __shared__ float red[256];

    float m = -1e30f;
    for (int c = tid; c < cols; c += 256) m = fmaxf(m, row[c]);
    red[tid] = m; __syncthreads();
    for (int s = 128; s > 0; s >>= 1) {
        if (tid < s) red[tid] = fmaxf(red[tid], red[tid + s]);
        __syncthreads();
    }
    m = red[0]; __syncthreads();

    float sum = 0.f;
    for (int c = tid; c < cols; c += 256) {
        float v = __expf(row[c] - m);
        row[c] = v;
        sum += v;
    }
    red[tid] = sum; __syncthreads();
    for (int s = 128; s > 0; s >>= 1) {
        if (tid < s) red[tid] += red[tid + s];
        __syncthreads();
    }
    float inv = 1.f / red[0];
    for (int c = tid; c < cols; c += 256) row[c] *= inv;
}

// ---------------- fused concat + final FC ([768] -> 32) --------------------
__global__ void k_final(const float* __restrict__ d, const float* __restrict__ ai,
                        const float* __restrict__ ae, const float* __restrict__ W,
                        const float* __restrict__ b, float* __restrict__ out, int M)
{
    __shared__ float s_in[8][768];
    int r0 = blockIdx.x * 8;
    int tid = threadIdx.x;   // 256
    for (int idx = tid; idx < 8 * 768; idx += 256) {
        int rr = idx / 768, cc = idx - rr * 768;
        int r = r0 + rr;
        float v = 0.f;
        if (r < M) {
            if (cc < 256)      v = d [(size_t)r * 256 + cc];
            else if (cc < 512) v = ai[(size_t)r * 256 + cc - 256];
            else               v = ae[(size_t)r * 256 + cc - 512];
        }
        s_in[rr][cc] = v;
    }
    __syncthreads();
    int rr = tid >> 5, j = tid & 31;
    int r = r0 + rr;
    if (r < M) {
        float acc = b[j];
#pragma unroll 8
        for (int k = 0; k < 768; k++) acc += s_in[rr][k] * W[k * 32 + j];
        out[(size_t)r * 32 + j] = acc;
    }
}

// ---------------- host orchestration ---------------------------------------
static inline void launch_gemm(const float* A, const float* B, float* C,
                               const float* bias, int M, int N, int K,
                               bool transb, bool do_bias, bool relu)
{
    dim3 grid(N / 128, (M + 127) / 128);
    if (transb) {
        tgemm<true, false, false><<<grid, 256>>>(A, B, C, nullptr, M, N, K);
    } else if (do_bias && relu) {
        tgemm<false, true, true><<<grid, 256>>>(A, B, C, bias, M, N, K);
    } else {
        tgemm<false, false, false><<<grid, 256>>>(A, B, C, nullptr, M, N, K);
    }
}

struct Ptrs {
    float *hd, *hi, *he, *ie, *ee, *ssrc, *sdst, *gat, *dd, *ii, *ev, *S, *atti, *atte;
    int *deg, *off, *cur, *csr;
};

static void run_gat(const float* x, const float* W, const float* a_src,
                    const float* a_dst, const float* bias,
                    const int* esrc, const int* edst,
                    int N, int E, int Din, float* hbuf, float* gat_out, const Ptrs& p)
{
    launch_gemm(x, W, hbuf, nullptr, N, HD, Din, false, false, false);
    k_scores<<<N, 128>>>(hbuf, a_src, a_dst, p.ssrc, p.sdst, N);
    k_set_deg1<<<(N + 255) / 256, 256>>>(p.deg, N);
    k_count<<<(E + 255) / 256 > 2048 ? 2048 : (E + 255) / 256, 256>>>(edst, p.deg, E);
    k_exscan<<<1, 1024>>>(p.deg, p.off, p.cur, N);
    k_fill<<<(E + 255) / 256 > 2048 ? 2048 : (E + 255) / 256, 256>>>(esrc, edst, p.cur, p.csr, E);
    k_fill_self<<<(N + 255) / 256, 256>>>(p.cur, p.csr, N);
    k_gat_agg<<<N, 256>>>(hbuf, p.ssrc, p.sdst, p.off, p.csr, bias, gat_out, N);
}

extern "C" void kernel_launch(void* const* d_in, const int* in_sizes, int n_in,
                              void* d_out, int out_size)
{
    const float* x_d     = (const float*)d_in[0];
    const int*   idx_i   = (const int*)  d_in[1];
    const int*   idx_e   = (const int*)  d_in[2];
    const int*   eidx_d  = (const int*)  d_in[3];
    const int*   eidx_i  = (const int*)  d_in[4];
    const int*   eidx_e  = (const int*)  d_in[5];
    const float* emb_i   = (const float*)d_in[6];
    const float* emb_e   = (const float*)d_in[7];
    const float* Wd      = (const float*)d_in[8];
    const float* a_src_d = (const float*)d_in[9];
    const float* a_dst_d = (const float*)d_in[10];
    const float* bd      = (const float*)d_in[11];
    const float* Wi      = (const float*)d_in[12];
    const float* a_src_i = (const float*)d_in[13];
    const float* a_dst_i = (const float*)d_in[14];
    const float* bi      = (const float*)d_in[15];
    const float* We      = (const float*)d_in[16];
    const float* a_src_e = (const float*)d_in[17];
    const float* a_dst_e = (const float*)d_in[18];
    const float* be      = (const float*)d_in[19];
    const float* W_dfc   = (const float*)d_in[20];
    const float* b_dfc   = (const float*)d_in[21];
    const float* W_ifc   = (const float*)d_in[22];
    const float* b_ifc   = (const float*)d_in[23];
    const float* W_efc   = (const float*)d_in[24];
    const float* b_efc   = (const float*)d_in[25];
    const float* W_fc    = (const float*)d_in[26];
    const float* b_fc    = (const float*)d_in[27];
    float* out = (float*)d_out;

    const int Din = 512;
    const int Nd = in_sizes[0] / Din;
    const int Ni = in_sizes[1];
    const int Ne = in_sizes[2];
    const int Ed = in_sizes[3] / 2;
    const int Ei = in_sizes[4] / 2;
    const int Ee = in_sizes[5] / 2;

    Ptrs p;
    cudaGetSymbolAddress((void**)&p.hd,   g_hd);
    cudaGetSymbolAddress((void**)&p.hi,   g_hi);
    cudaGetSymbolAddress((void**)&p.he,   g_he);
    cudaGetSymbolAddress((void**)&p.ie,   g_ie);
    cudaGetSymbolAddress((void**)&p.ee,   g_ee);
    cudaGetSymbolAddress((void**)&p.ssrc, g_ssrc);
    cudaGetSymbolAddress((void**)&p.sdst, g_sdst);
    cudaGetSymbolAddress((void**)&p.gat,  g_gat);
    cudaGetSymbolAddress((void**)&p.dd,   g_dd);
    cudaGetSymbolAddress((void**)&p.ii,   g_ii);
    cudaGetSymbolAddress((void**)&p.ev,   g_ev);
    cudaGetSymbolAddress((void**)&p.S,    g_S);
    cudaGetSymbolAddress((void**)&p.atti, g_atti);
    cudaGetSymbolAddress((void**)&p.atte, g_atte);
    cudaGetSymbolAddress((void**)&p.deg,  g_deg);
    cudaGetSymbolAddress((void**)&p.off,  g_off);
    cudaGetSymbolAddress((void**)&p.cur,  g_cur);
    cudaGetSymbolAddress((void**)&p.csr,  g_csr);

    // embedding lookups
    k_gather_emb<<<2048, 256>>>(emb_i, idx_i, p.ie, Ni);
    k_gather_emb<<<2048, 256>>>(emb_e, idx_e, p.ee, Ne);

    // dialogue branch: GAT + relu FC
    run_gat(x_d, Wd, a_src_d, a_dst_d, bd, eidx_d, eidx_d + Ed, Nd, Ed, Din, p.hd, p.gat, p);
    launch_gemm(p.gat, W_dfc, p.dd, b_dfc, Nd, DD, DD, false, true, true);

    // intention branch
    run_gat(p.ie, Wi, a_src_i, a_dst_i, bi, eidx_i, eidx_i + Ei, Ni, Ei, DD, p.hi, p.gat, p);
    launch_gemm(p.gat, W_ifc, p.ii, b_ifc, Ni, DD, DD, false, true, true);

    // emotion branch
    run_gat(p.ee, We, a_src_e, a_dst_e, be, eidx_e, eidx_e + Ee, Ne, Ee, DD, p.he, p.gat, p);
    launch_gemm(p.gat, W_efc, p.ev, b_efc, Ne, DD, DD, false, true, true);

    // cross attention: att_i = softmax(d @ i^T) @ i
    launch_gemm(p.dd, p.ii, p.S, nullptr, Nd, Ni, DD, true, false, false);
    k_softmax<<<Nd, 256>>>(p.S, Ni);
    launch_gemm(p.S, p.ii, p.atti, nullptr, Nd, DD, Ni, false, false, false);

    // att_e = softmax(d @ e^T) @ e
    launch_gemm(p.dd, p.ev, p.S, nullptr, Nd, Ne, DD, true, false, false);
    k_softmax<<<Nd, 256>>>(p.S, Ne);
    launch_gemm(p.S, p.ev, p.atte, nullptr, Nd, DD, Ne, false, false, false);

    // fused concat + final FC
    k_final<<<(Nd + 7) / 8, 256>>>(p.dd, p.atti, p.atte, W_fc, b_fc, out, Nd);
}

// round 3
// speedup vs baseline: 2.8563x; 1.2014x over previous
#include <cuda_runtime.h>
#include <math.h>
#include <stdint.h>

#define HEADS 4
#define DD 256
#define HD 1024            // HEADS * DD

#define MAXND 20000
#define MAXNI 4096
#define MAXED 640000
#define MAXET (MAXED + MAXND)

// ---------------- scratch (device globals; no allocation allowed) ----------
__device__ float g_hd  [(size_t)MAXND * HD];
__device__ float g_hi  [(size_t)MAXNI * HD];
__device__ float g_he  [(size_t)MAXNI * HD];
__device__ float g_ie  [(size_t)MAXNI * DD];
__device__ float g_ee  [(size_t)MAXNI * DD];
__device__ float g_ssrc[(size_t)MAXND * HEADS];
__device__ float g_sdst[(size_t)MAXND * HEADS];
__device__ int   g_deg [MAXND];
__device__ int   g_off [MAXND + 1];
__device__ int   g_cur [MAXND];
__device__ int   g_csr [MAXET];
__device__ float g_gat [(size_t)MAXND * DD];
__device__ float g_dd  [(size_t)MAXND * DD];
__device__ float g_ii  [(size_t)MAXNI * DD];
__device__ float g_ev  [(size_t)MAXNI * DD];
__device__ float g_S   [(size_t)MAXND * 4096];
__device__ float g_atti[(size_t)MAXND * DD];
__device__ float g_atte[(size_t)MAXND * DD];

// ---------------- helpers ---------------------------------------------------
__device__ __forceinline__ uint32_t f2tf(float f) {
    uint32_t u;
    asm("cvt.rna.tf32.f32 %0, %1;" : "=r"(u) : "f"(f));
    return u;
}
__device__ __forceinline__ uint32_t smem_u32(const void* p) {
    uint32_t a;
    asm("{ .reg .u64 t; cvta.to.shared.u64 t, %1; cvt.u32.u64 %0, t; }"
        : "=r"(a) : "l"(p));
    return a;
}
#define CPASYNC16(d, s, sz) \
    asm volatile("cp.async.cg.shared.global [%0], [%1], 16, %2;" \
                 :: "r"(d), "l"(s), "r"(sz))
#define CPCOMMIT() asm volatile("cp.async.commit_group;")

// ---------------- tf32 tensor-core GEMM, cp.async 2-stage pipeline ----------
// C[M,N] = A[M,K] @ B  (B: [K,N] row-major; [N,K] row-major if TRANSB)
// BM=BN=128, BK=16, 256 threads = 8 warps (4x2), warp tile 32x64 (m16n8k8).
// Requires K % 16 == 0, N % 128 == 0; M guarded.
// Smem: As[m][k] pad 20 (conflict-free), Bs NN [k][n] pad 136, TB [n][k] pad 20.
template<bool TRANSB, bool BIAS, bool RELU>
__global__ __launch_bounds__(256)
void tgemm(const float* __restrict__ A, const float* __restrict__ B,
           float* __restrict__ C, const float* __restrict__ bias,
           int M, int N, int K)
{
    __shared__ float As[2][128 * 20];
    __shared__ float Bs[2][2560];      // NN uses 16*136=2176, TB uses 128*20=2560

    const int tid  = threadIdx.x;
    const int warp = tid >> 5, lane = tid & 31;
    const int g    = lane >> 2, tig = lane & 3;
    const int wm   = (warp >> 1) * 32;
    const int wn   = (warp & 1) * 64;
    const int row0 = blockIdx.y * 128, col0 = blockIdx.x * 128;

    float c[2][8][4];
#pragma unroll
    for (int i = 0; i < 2; i++)
#pragma unroll
        for (int j = 0; j < 8; j++)
#pragma unroll
            for (int q = 0; q < 4; q++) c[i][j][q] = 0.f;

    uint32_t asb[2], bsb[2];
    asb[0] = smem_u32(&As[0][0]); asb[1] = smem_u32(&As[1][0]);
    bsb[0] = smem_u32(&Bs[0][0]); bsb[1] = smem_u32(&Bs[1][0]);

    const int nIter = K >> 4;

    auto load_stage = [&](int s, int k0) {
#pragma unroll
        for (int i = 0; i < 2; i++) {        // A: 128 rows x 16 k = 512 chunks
            int f = tid + 256 * i;
            int row = f >> 2, c4 = (f & 3) * 4;
            int gr = row0 + row;
            const float* src = A + (size_t)(gr < M ? gr : M - 1) * K + k0 + c4;
            CPASYNC16(asb[s] + (row * 20 + c4) * 4, src, (gr < M) ? 16 : 0);
        }
#pragma unroll
        for (int i = 0; i < 2; i++) {        // B: 512 chunks
            int f = tid + 256 * i;
            if (TRANSB) {
                int n = f >> 2, k4 = (f & 3) * 4;
                const float* src = B + (size_t)(col0 + n) * K + k0 + k4;
                CPASYNC16(bsb[s] + (n * 20 + k4) * 4, src, 16);
            } else {
                int k = f >> 5, n4 = (f & 31) * 4;
                const float* src = B + (size_t)(k0 + k) * N + col0 + n4;
                CPASYNC16(bsb[s] + (k * 136 + n4) * 4, src, 16);
            }
        }
        CPCOMMIT();
    };

    load_stage(0, 0);

    for (int it = 0; it < nIter; it++) {
        if (it + 1 < nIter) {
            load_stage((it + 1) & 1, (it + 1) << 4);
            asm volatile("cp.async.wait_group 1;");
        } else {
            asm volatile("cp.async.wait_group 0;");
        }
        __syncthreads();

        const float* as_ = As[it & 1];
        const float* bs_ = Bs[it & 1];

#pragma unroll
        for (int ks = 0; ks < 2; ks++) {
            const int kk = ks * 8;
            uint32_t af[2][4], bf[8][2];
#pragma unroll
            for (int i = 0; i < 2; i++) {
                int m = wm + i * 16 + g;
                af[i][0] = f2tf(as_[(size_t)m * 20 + kk + tig]);
                af[i][1] = f2tf(as_[(size_t)(m + 8) * 20 + kk + tig]);
                af[i][2] = f2tf(as_[(size_t)m * 20 + kk + tig + 4]);
                af[i][3] = f2tf(as_[(size_t)(m + 8) * 20 + kk + tig + 4]);
            }
#pragma unroll
            for (int j = 0; j < 8; j++) {
                int n = wn + j * 8 + g;
                if (TRANSB) {
                    bf[j][0] = f2tf(bs_[(size_t)n * 20 + kk + tig]);
                    bf[j][1] = f2tf(bs_[(size_t)n * 20 + kk + tig + 4]);
                } else {
                    bf[j][0] = f2tf(bs_[(size_t)(kk + tig) * 136 + n]);
                    bf[j][1] = f2tf(bs_[(size_t)(kk + tig + 4) * 136 + n]);
                }
            }
#pragma unroll
            for (int i = 0; i < 2; i++)
#pragma unroll
                for (int j = 0; j < 8; j++) {
                    asm volatile(
                        "mma.sync.aligned.m16n8k8.row.col.f32.tf32.tf32.f32 "
                        "{%0,%1,%2,%3}, {%4,%5,%6,%7}, {%8,%9}, {%0,%1,%2,%3};"
                        : "+f"(c[i][j][0]), "+f"(c[i][j][1]),
                          "+f"(c[i][j][2]), "+f"(c[i][j][3])
                        : "r"(af[i][0]), "r"(af[i][1]), "r"(af[i][2]), "r"(af[i][3]),
                          "r"(bf[j][0]), "r"(bf[j][1]));
                }
        }
        __syncthreads();
    }

    // ---- epilogue ----
#pragma unroll
    for (int i = 0; i < 2; i++) {
        int r0 = row0 + wm + i * 16 + g;
        int r1 = r0 + 8;
#pragma unroll
        for (int j = 0; j < 8; j++) {
            int cc = col0 + wn + j * 8 + tig * 2;
            float v0 = c[i][j][0], v1 = c[i][j][1];
            float v2 = c[i][j][2], v3 = c[i][j][3];
            if (BIAS) {
                float bb0 = bias[cc], bb1 = bias[cc + 1];
                v0 += bb0; v1 += bb1; v2 += bb0; v3 += bb1;
            }
            if (RELU) {
                v0 = fmaxf(v0, 0.f); v1 = fmaxf(v1, 0.f);
                v2 = fmaxf(v2, 0.f); v3 = fmaxf(v3, 0.f);
            }
            if (r0 < M) *(float2*)(C + (size_t)r0 * N + cc) = make_float2(v0, v1);
            if (r1 < M) *(float2*)(C + (size_t)r1 * N + cc) = make_float2(v2, v3);
        }
    }
}

// ---------------- misc small kernels ---------------------------------------
__global__ void k_gather_emb(const float* __restrict__ table, const int* __restrict__ idx,
                             float* __restrict__ out, int N)
{
    int i = blockIdx.x * blockDim.x + threadIdx.x;
    int total = N * DD;
    for (; i < total; i += gridDim.x * blockDim.x) {
        int n = i / DD, c = i - n * DD;
        out[i] = table[(size_t)idx[n] * DD + c];
    }
}

__global__ void k_scores(const float* __restrict__ h, const float* __restrict__ a_src,
                         const float* __restrict__ a_dst,
                         float* __restrict__ ssrc, float* __restrict__ sdst, int N)
{
    int n = blockIdx.x;
    int tid = threadIdx.x;        // 128
    int hh = tid >> 5, lane = tid & 31;
    const float* hr = h + (size_t)n * HD + hh * DD;
    float s1 = 0.f, s2 = 0.f;
    for (int c = lane; c < DD; c += 32) {
        float v = hr[c];
        s1 += v * a_src[hh * DD + c];
        s2 += v * a_dst[hh * DD + c];
    }
#pragma unroll
    for (int o = 16; o > 0; o >>= 1) {
        s1 += __shfl_down_sync(0xffffffffu, s1, o);
        s2 += __shfl_down_sync(0xffffffffu, s2, o);
    }
    if (lane == 0) { ssrc[n * HEADS + hh] = s1; sdst[n * HEADS + hh] = s2; }
}

__global__ void k_set_deg1(int* deg, int N)
{
    int i = blockIdx.x * blockDim.x + threadIdx.x;
    if (i < N) deg[i] = 1;
}
__global__ void k_count(const int* __restrict__ dst, int* __restrict__ deg, int E)
{
    int i = blockIdx.x * blockDim.x + threadIdx.x;
    for (; i < E; i += gridDim.x * blockDim.x) atomicAdd(&deg[dst[i]], 1);
}

// warp-shuffle based exclusive scan, 1024 threads, chunked
__global__ void k_exscan(const int* __restrict__ deg, int* __restrict__ off,
                         int* __restrict__ cur, int N)
{
    __shared__ int wsum[32];
    __shared__ int carry_s;
    int tid = threadIdx.x, lane = tid & 31, w = tid >> 5;
    if (tid == 0) carry_s = 0;
    __syncthreads();
    for (int base = 0; base < N; base += 1024) {
        int i = base + tid;
        int v = (i < N) ? deg[i] : 0;
        int x = v;
#pragma unroll
        for (int o = 1; o < 32; o <<= 1) {
            int t = __shfl_up_sync(0xffffffffu, x, o);
            if (lane >= o) x += t;
        }
        if (lane == 31) wsum[w] = x;
        __syncthreads();
        if (w == 0) {
            int s = wsum[lane];
#pragma unroll
            for (int o = 1; o < 32; o <<= 1) {
                int t = __shfl_up_sync(0xffffffffu, s, o);
                if (lane >= o) s += t;
            }
            wsum[lane] = s;
        }
        __syncthreads();
        int excl = carry_s + (w > 0 ? wsum[w - 1] : 0) + x - v;
        if (i < N) { off[i] = excl; cur[i] = excl; }
        __syncthreads();
        if (tid == 0) carry_s += wsum[31];
        __syncthreads();
    }
    if (tid == 0) off[N] = carry_s;
}
__global__ void k_fill(const int* __restrict__ src, const int* __restrict__ dst,
                       int* __restrict__ cur, int* __restrict__ csr, int E)
{
    int i = blockIdx.x * blockDim.x + threadIdx.x;
    for (; i < E; i += gridDim.x * blockDim.x) {
        int p = atomicAdd(&cur[dst[i]], 1);
        csr[p] = src[i];
    }
}
__global__ void k_fill_self(int* __restrict__ cur, int* __restrict__ csr, int N)
{
    int i = blockIdx.x * blockDim.x + threadIdx.x;
    if (i < N) { int p = atomicAdd(&cur[i], 1); csr[p] = i; }
}

// ---------------- GAT aggregation: one block per destination node ----------
#define AGG_CHUNK 512
__global__ void k_gat_agg(const float* __restrict__ h,      // [N, HD]
                          const float* __restrict__ ssrc,   // [N, 4]
                          const float* __restrict__ sdst,   // [N, 4]
                          const int* __restrict__ off, const int* __restrict__ csr,
                          const float* __restrict__ bias,   // [256]
                          float* __restrict__ out, int N)   // [N, 256]
{
    const int n = blockIdx.x;
    const int tid = threadIdx.x;      // 256
    const int e0 = off[n], e1 = off[n + 1];

    __shared__ int    s_src[AGG_CHUNK];
    __shared__ float  s_w[AGG_CHUNK * 4];
    __shared__ float4 red[256];
    __shared__ float  s_m[4], s_s[4];
    __shared__ float  s_out[1024];

    float sd[4];
#pragma unroll
    for (int hh = 0; hh < 4; hh++) sd[hh] = sdst[n * 4 + hh];

    float mloc[4] = {-1e30f, -1e30f, -1e30f, -1e30f};
    for (int e = e0 + tid; e < e1; e += 256) {
        int s = csr[e];
#pragma unroll
        for (int hh = 0; hh < 4; hh++) {
            float v = ssrc[s * 4 + hh] + sd[hh];
            v = v > 0.f ? v : 0.2f * v;
            mloc[hh] = fmaxf(mloc[hh], v);
        }
    }
    red[tid] = make_float4(mloc[0], mloc[1], mloc[2], mloc[3]);
    __syncthreads();
    for (int s = 128; s > 0; s >>= 1) {
        if (tid < s) {
            float4 a = red[tid], b = red[tid + s];
            a.x = fmaxf(a.x, b.x); a.y = fmaxf(a.y, b.y);
            a.z = fmaxf(a.z, b.z); a.w = fmaxf(a.w, b.w);
            red[tid] = a;
        }
        __syncthreads();
    }
    if (tid < 4) s_m[tid] = ((float*)&red[0])[tid];
    __syncthreads();
    float m0 = s_m[0], m1 = s_m[1], m2 = s_m[2], m3 = s_m[3];

    const int hh_ = tid >> 6;
    const int cb  = tid & 63;
    float acc0 = 0.f, acc1 = 0.f, acc2 = 0.f, acc3 = 0.f;
    float wsum[4] = {0.f, 0.f, 0.f, 0.f};

    for (int c0 = e0; c0 < e1; c0 += AGG_CHUNK) {
        int cnt = min(AGG_CHUNK, e1 - c0);
        for (int j = tid; j < cnt; j += 256) {
            int s = csr[c0 + j];
            s_src[j] = s;
            float v0 = ssrc[s * 4 + 0] + sd[0]; v0 = v0 > 0.f ? v0 : 0.2f * v0;
            float v1 = ssrc[s * 4 + 1] + sd[1]; v1 = v1 > 0.f ? v1 : 0.2f * v1;
            float v2 = ssrc[s * 4 + 2] + sd[2]; v2 = v2 > 0.f ? v2 : 0.2f * v2;
            float v3 = ssrc[s * 4 + 3] + sd[3]; v3 = v3 > 0.f ? v3 : 0.2f * v3;
            float w0 = __expf(v0 - m0), w1 = __expf(v1 - m1);
            float w2 = __expf(v2 - m2), w3 = __expf(v3 - m3);
            s_w[j * 4 + 0] = w0; s_w[j * 4 + 1] = w1;
            s_w[j * 4 + 2] = w2; s_w[j * 4 + 3] = w3;
            wsum[0] += w0; wsum[1] += w1; wsum[2] += w2; wsum[3] += w3;
        }
        __syncthreads();
        for (int j = 0; j < cnt; j++) {
            int s = s_src[j];
            float w = s_w[j * 4 + hh_];
            const float* hr = h + (size_t)s * HD + hh_ * DD + cb;
            acc0 += w * hr[0];
            acc1 += w * hr[64];
            acc2 += w * hr[128];
            acc3 += w * hr[192];
        }
        __syncthreads();
    }

    red[tid] = make_float4(wsum[0], wsum[1], wsum[2], wsum[3]);
    __syncthreads();
    for (int s = 128; s > 0; s >>= 1) {
        if (tid < s) {
            float4 a = red[tid], b = red[tid + s];
            a.x += b.x; a.y += b.y; a.z += b.z; a.w += b.w;
            red[tid] = a;
        }
        __syncthreads();
    }
    if (tid < 4) s_s[tid] = ((float*)&red[0])[tid];

    s_out[hh_ * 256 + cb]       = acc0;
    s_out[hh_ * 256 + cb + 64]  = acc1;
    s_out[hh_ * 256 + cb + 128] = acc2;
    s_out[hh_ * 256 + cb + 192] = acc3;
    __syncthreads();

    {
        int c = tid;
        float r = 0.f;
#pragma unroll
        for (int hh = 0; hh < 4; hh++)
            r += s_out[hh * 256 + c] / (s_s[hh] + 1e-16f);
        out[(size_t)n * DD + c] = 0.25f * r + bias[c];
    }
}

// ---------------- row softmax -----------------------------------------------
__global__ void k_softmax(float* __restrict__ S, int cols)
{
    int r = blockIdx.x;
    float* row = S + (size_t)r * cols;
    int tid = threadIdx.x;   // 256
    __shared__ float red[256];

    float m = -1e30f;
    for (int c = tid; c < cols; c += 256) m = fmaxf(m, row[c]);
    red[tid] = m; __syncthreads();
    for (int s = 128; s > 0; s >>= 1) {
        if (tid < s) red[tid] = fmaxf(red[tid], red[tid + s]);
        __syncthreads();
    }
    m = red[0]; __syncthreads();

    float sum = 0.f;
    for (int c = tid; c < cols; c += 256) {
        float v = __expf(row[c] - m);
        row[c] = v;
        sum += v;
    }
    red[tid] = sum; __syncthreads();
    for (int s = 128; s > 0; s >>= 1) {
        if (tid < s) red[tid] += red[tid + s];
        __syncthreads();
    }
    float inv = 1.f / red[0];
    for (int c = tid; c < cols; c += 256) row[c] *= inv;
}

// ---------------- fused concat + final FC ([768] -> 32) --------------------
__global__ void k_final(const float* __restrict__ d, const float* __restrict__ ai,
                        const float* __restrict__ ae, const float* __restrict__ W,
                        const float* __restrict__ b, float* __restrict__ out, int M)
{
    __shared__ float s_in[8][768];
    int r0 = blockIdx.x * 8;
    int tid = threadIdx.x;   // 256
    for (int idx = tid; idx < 8 * 768; idx += 256) {
        int rr = idx / 768, cc = idx - rr * 768;
        int r = r0 + rr;
        float v = 0.f;
        if (r < M) {
            if (cc < 256)      v = d [(size_t)r * 256 + cc];
            else if (cc < 512) v = ai[(size_t)r * 256 + cc - 256];
            else               v = ae[(size_t)r * 256 + cc - 512];
        }
        s_in[rr][cc] = v;
    }
    __syncthreads();
    int rr = tid >> 5, j = tid & 31;
    int r = r0 + rr;
    if (r < M) {
        float acc = b[j];
#pragma unroll 8
        for (int k = 0; k < 768; k++) acc += s_in[rr][k] * W[k * 32 + j];
        out[(size_t)r * 32 + j] = acc;
    }
}

// ---------------- host orchestration ---------------------------------------
static inline void launch_gemm(const float* A, const float* B, float* C,
                               const float* bias, int M, int N, int K,
                               bool transb, bool do_bias, bool relu)
{
    dim3 grid(N / 128, (M + 127) / 128);
    if (transb) {
        tgemm<true, false, false><<<grid, 256>>>(A, B, C, nullptr, M, N, K);
    } else if (do_bias && relu) {
        tgemm<false, true, true><<<grid, 256>>>(A, B, C, bias, M, N, K);
    } else {
        tgemm<false, false, false><<<grid, 256>>>(A, B, C, nullptr, M, N, K);
    }
}

struct Ptrs {
    float *hd, *hi, *he, *ie, *ee, *ssrc, *sdst, *gat, *dd, *ii, *ev, *S, *atti, *atte;
    int *deg, *off, *cur, *csr;
};

static void run_gat(const float* x, const float* W, const float* a_src,
                    const float* a_dst, const float* bias,
                    const int* esrc, const int* edst,
                    int N, int E, int Din, float* hbuf, float* gat_out, const Ptrs& p)
{
    launch_gemm(x, W, hbuf, nullptr, N, HD, Din, false, false, false);
    k_scores<<<N, 128>>>(hbuf, a_src, a_dst, p.ssrc, p.sdst, N);
    k_set_deg1<<<(N + 255) / 256, 256>>>(p.deg, N);
    k_count<<<(E + 255) / 256 > 2048 ? 2048 : (E + 255) / 256, 256>>>(edst, p.deg, E);
    k_exscan<<<1, 1024>>>(p.deg, p.off, p.cur, N);
    k_fill<<<(E + 255) / 256 > 2048 ? 2048 : (E + 255) / 256, 256>>>(esrc, edst, p.cur, p.csr, E);
    k_fill_self<<<(N + 255) / 256, 256>>>(p.cur, p.csr, N);
    k_gat_agg<<<N, 256>>>(hbuf, p.ssrc, p.sdst, p.off, p.csr, bias, gat_out, N);
}

extern "C" void kernel_launch(void* const* d_in, const int* in_sizes, int n_in,
                              void* d_out, int out_size)
{
    const float* x_d     = (const float*)d_in[0];
    const int*   idx_i   = (const int*)  d_in[1];
    const int*   idx_e   = (const int*)  d_in[2];
    const int*   eidx_d  = (const int*)  d_in[3];
    const int*   eidx_i  = (const int*)  d_in[4];
    const int*   eidx_e  = (const int*)  d_in[5];
    const float* emb_i   = (const float*)d_in[6];
    const float* emb_e   = (const float*)d_in[7];
    const float* Wd      = (const float*)d_in[8];
    const float* a_src_d = (const float*)d_in[9];
    const float* a_dst_d = (const float*)d_in[10];
    const float* bd      = (const float*)d_in[11];
    const float* Wi      = (const float*)d_in[12];
    const float* a_src_i = (const float*)d_in[13];
    const float* a_dst_i = (const float*)d_in[14];
    const float* bi      = (const float*)d_in[15];
    const float* We      = (const float*)d_in[16];
    const float* a_src_e = (const float*)d_in[17];
    const float* a_dst_e = (const float*)d_in[18];
    const float* be      = (const float*)d_in[19];
    const float* W_dfc   = (const float*)d_in[20];
    const float* b_dfc   = (const float*)d_in[21];
    const float* W_ifc   = (const float*)d_in[22];
    const float* b_ifc   = (const float*)d_in[23];
    const float* W_efc   = (const float*)d_in[24];
    const float* b_efc   = (const float*)d_in[25];
    const float* W_fc    = (const float*)d_in[26];
    const float* b_fc    = (const float*)d_in[27];
    float* out = (float*)d_out;

    const int Din = 512;
    const int Nd = in_sizes[0] / Din;
    const int Ni = in_sizes[1];
    const int Ne = in_sizes[2];
    const int Ed = in_sizes[3] / 2;
    const int Ei = in_sizes[4] / 2;
    const int Ee = in_sizes[5] / 2;

    Ptrs p;
    cudaGetSymbolAddress((void**)&p.hd,   g_hd);
    cudaGetSymbolAddress((void**)&p.hi,   g_hi);
    cudaGetSymbolAddress((void**)&p.he,   g_he);
    cudaGetSymbolAddress((void**)&p.ie,   g_ie);
    cudaGetSymbolAddress((void**)&p.ee,   g_ee);
    cudaGetSymbolAddress((void**)&p.ssrc, g_ssrc);
    cudaGetSymbolAddress((void**)&p.sdst, g_sdst);
    cudaGetSymbolAddress((void**)&p.gat,  g_gat);
    cudaGetSymbolAddress((void**)&p.dd,   g_dd);
    cudaGetSymbolAddress((void**)&p.ii,   g_ii);
    cudaGetSymbolAddress((void**)&p.ev,   g_ev);
    cudaGetSymbolAddress((void**)&p.S,    g_S);
    cudaGetSymbolAddress((void**)&p.atti, g_atti);
    cudaGetSymbolAddress((void**)&p.atte, g_atte);
    cudaGetSymbolAddress((void**)&p.deg,  g_deg);
    cudaGetSymbolAddress((void**)&p.off,  g_off);
    cudaGetSymbolAddress((void**)&p.cur,  g_cur);
    cudaGetSymbolAddress((void**)&p.csr,  g_csr);

    // embedding lookups
    k_gather_emb<<<2048, 256>>>(emb_i, idx_i, p.ie, Ni);
    k_gather_emb<<<2048, 256>>>(emb_e, idx_e, p.ee, Ne);

    // dialogue branch: GAT + relu FC
    run_gat(x_d, Wd, a_src_d, a_dst_d, bd, eidx_d, eidx_d + Ed, Nd, Ed, Din, p.hd, p.gat, p);
    launch_gemm(p.gat, W_dfc, p.dd, b_dfc, Nd, DD, DD, false, true, true);

    // intention branch
    run_gat(p.ie, Wi, a_src_i, a_dst_i, bi, eidx_i, eidx_i + Ei, Ni, Ei, DD, p.hi, p.gat, p);
    launch_gemm(p.gat, W_ifc, p.ii, b_ifc, Ni, DD, DD, false, true, true);

    // emotion branch
    run_gat(p.ee, We, a_src_e, a_dst_e, be, eidx_e, eidx_e + Ee, Ne, Ee, DD, p.he, p.gat, p);
    launch_gemm(p.gat, W_efc, p.ev, b_efc, Ne, DD, DD, false, true, true);

    // cross attention: att_i = softmax(d @ i^T) @ i
    launch_gemm(p.dd, p.ii, p.S, nullptr, Nd, Ni, DD, true, false, false);
    k_softmax<<<Nd, 256>>>(p.S, Ni);
    launch_gemm(p.S, p.ii, p.atti, nullptr, Nd, DD, Ni, false, false, false);

    // att_e = softmax(d @ e^T) @ e
    launch_gemm(p.dd, p.ev, p.S, nullptr, Nd, Ne, DD, true, false, false);
    k_softmax<<<Nd, 256>>>(p.S, Ne);
    launch_gemm(p.S, p.ev, p.atte, nullptr, Nd, DD, Ne, false, false, false);

    // fused concat + final FC
    k_final<<<(Nd + 7) / 8, 256>>>(p.dd, p.atti, p.atte, W_fc, b_fc, out, Nd);
}